// round 15
// baseline (speedup 1.0000x reference)
#include <cuda_runtime.h>
#include <cuda_bf16.h>
#include <cstdint>

#define BATCH 8
#define NPOS 4096
#define CDIM 256

// Scratch: Q bf16 [b][n][32] (pre-scaled by log2e), K bf16 [b][n][32],
// V channel-major bf16 [b][c][n].
__device__ __nv_bfloat16 g_q[(size_t)BATCH * NPOS * 32];
__device__ __nv_bfloat16 g_k[(size_t)BATCH * NPOS * 32];
__device__ __nv_bfloat16 g_v[(size_t)BATCH * CDIM * NPOS];

// ---------------- helpers ----------------
__device__ __forceinline__ uint32_t smem_u32(const void* p) {
    uint32_t a;
    asm("{ .reg .u64 t; cvta.to.shared.u64 t, %1; cvt.u32.u64 %0, t; }" : "=r"(a) : "l"(p));
    return a;
}
__device__ __forceinline__ float ex2f(float x) {
    float y; asm("ex2.approx.f32 %0, %1;" : "=f"(y) : "f"(x)); return y;
}
__device__ __forceinline__ void sts32(uint32_t a, uint32_t v) {
    asm volatile("st.shared.b32 [%0], %1;" :: "r"(a), "r"(v));
}
__device__ __forceinline__ void sts128(uint32_t a, uint32_t v0, uint32_t v1,
                                       uint32_t v2, uint32_t v3) {
    asm volatile("st.shared.v4.b32 [%0], {%1, %2, %3, %4};"
                 :: "r"(a), "r"(v0), "r"(v1), "r"(v2), "r"(v3));
}
__device__ __forceinline__ void cp16(uint32_t dst, const void* src) {
    asm volatile("cp.async.cg.shared.global [%0], [%1], 16;" :: "r"(dst), "l"(src));
}
#define CP_COMMIT() asm volatile("cp.async.commit_group;" ::: "memory")
#define CP_WAIT(N)  asm volatile("cp.async.wait_group %0;" :: "n"(N) : "memory")

__device__ __forceinline__ void ldm_x4(uint32_t addr, uint32_t* r) {
    asm volatile("ldmatrix.sync.aligned.m8n8.x4.shared.b16 {%0,%1,%2,%3}, [%4];"
                 : "=r"(r[0]), "=r"(r[1]), "=r"(r[2]), "=r"(r[3]) : "r"(addr));
}
__device__ __forceinline__ void mma16816(float* c, const uint32_t* a, uint32_t b0, uint32_t b1) {
    asm volatile(
        "mma.sync.aligned.m16n8k16.row.col.f32.bf16.bf16.f32 "
        "{%0,%1,%2,%3}, {%4,%5,%6,%7}, {%8,%9}, {%0,%1,%2,%3};"
        : "+f"(c[0]), "+f"(c[1]), "+f"(c[2]), "+f"(c[3])
        : "r"(a[0]), "r"(a[1]), "r"(a[2]), "r"(a[3]), "r"(b0), "r"(b1));
}
__device__ __forceinline__ uint32_t bf2(float a, float b) {
    const __nv_bfloat162 t = __floats2bfloat162_rn(a, b);
    return *(const uint32_t*)&t;
}

#define LOG2E 1.4426950408889634f

// ================= Kernel A: fused transpose + projections on HMMA (R13) =================
#define PJ_XS  0
#define PJ_W   131072
#define PROJ_SMEM 166912

__global__ void __launch_bounds__(256) proj_kernel(
    const float* __restrict__ x,
    const float* __restrict__ Wq, const float* __restrict__ bq,
    const float* __restrict__ Wk, const float* __restrict__ bk,
    const float* __restrict__ Wv, const float* __restrict__ bv)
{
    extern __shared__ char psm[];
    const uint32_t sbp = smem_u32(psm);
    const int tid = threadIdx.x;
    const int w = tid >> 5, lane = tid & 31;
    const int lg = lane >> 2, ll = lane & 3;
    const int b  = blockIdx.y;
    const int n0 = blockIdx.x * 256;

    const int mo = (w & 1) * 32;
    const int nb = (w >> 1) * 64;

    const uint32_t a_off_w = (lane & 15) * 528 + ((lane >> 4) << 4);
    const int xrow = (lane & 7) + ((lane >> 4) << 3);
    const int xhb  = (lane >> 3) & 1;

    // ---- Phase X: transpose x -> xs ----
    {
        const float* xg = x + (((size_t)b * CDIM) << 12) + n0 + tid;
        const uint32_t rowbase = sbp + PJ_XS + tid * 512;
        const int nx7 = tid & 7;
#pragma unroll 1
        for (int ci = 0; ci < 8; ci++) {
            float xv[32];
#pragma unroll
            for (int c = 0; c < 32; c++)
                xv[c] = xg[((size_t)(ci * 32 + c)) << 12];
            uint32_t pk[16];
#pragma unroll
            for (int e = 0; e < 16; e++) pk[e] = bf2(xv[2 * e], xv[2 * e + 1]);
#pragma unroll
            for (int q = 0; q < 4; q++)
                sts128(rowbase + (uint32_t)(((ci * 4 + q) ^ nx7) << 4),
                       pk[4 * q], pk[4 * q + 1], pk[4 * q + 2], pk[4 * q + 3]);
        }
    }

#pragma unroll 1
    for (int oy = 0; oy < 5; oy++) {
        __syncthreads();

        {
            const int ob = oy * 64;
#pragma unroll
            for (int r = 0; r < 8; r++) {
                const int idx = tid + r * 256;
                const int row = idx >> 5;
                const int cq  = (idx & 31) * 8;
                const int og  = ob + row;
                const float* wrow;
                if (og < 32)      wrow = Wq + og * CDIM;
                else if (og < 64) wrow = Wk + (og - 32) * CDIM;
                else              wrow = Wv + (og - 64) * CDIM;
                const float4 v0 = *(const float4*)(wrow + cq);
                const float4 v1 = *(const float4*)(wrow + cq + 4);
                const uint32_t base = sbp + PJ_W + row * 528 + cq * 2;
                sts32(base + 0,  bf2(v0.x, v0.y));
                sts32(base + 4,  bf2(v0.z, v0.w));
                sts32(base + 8,  bf2(v1.x, v1.y));
                sts32(base + 12, bf2(v1.z, v1.w));
            }
        }
        __syncthreads();

        float of[2][8][4];
#pragma unroll
        for (int mt = 0; mt < 2; mt++)
#pragma unroll
            for (int nf = 0; nf < 8; nf++)
#pragma unroll
                for (int r = 0; r < 4; r++) of[mt][nf][r] = 0.0f;

#pragma unroll 1
        for (int i = 0; i < 8; i++) {
            uint32_t afr[2][2][4];
#pragma unroll
            for (int mt = 0; mt < 2; mt++)
#pragma unroll
                for (int kk = 0; kk < 2; kk++)
                    ldm_x4(sbp + PJ_W + (uint32_t)(mo + mt * 16) * 528 + a_off_w +
                               i * 64 + kk * 32,
                           afr[mt][kk]);
#pragma unroll
            for (int np = 0; np < 4; np++) {
                const int row = nb + np * 16 + xrow;
                const uint32_t rb = sbp + PJ_XS + (uint32_t)row * 512;
                const int r7 = row & 7;
                uint32_t bfr[2][4];
                ldm_x4(rb + (uint32_t)(((i * 4 + 0 + xhb) ^ r7) << 4), bfr[0]);
                ldm_x4(rb + (uint32_t)(((i * 4 + 2 + xhb) ^ r7) << 4), bfr[1]);
#pragma unroll
                for (int mt = 0; mt < 2; mt++)
#pragma unroll
                    for (int nf2 = 0; nf2 < 2; nf2++) {
                        const int nf = np * 2 + nf2;
                        mma16816(of[mt][nf], afr[mt][0], bfr[0][nf2 * 2], bfr[0][nf2 * 2 + 1]);
                        mma16816(of[mt][nf], afr[mt][1], bfr[1][nf2 * 2], bfr[1][nf2 * 2 + 1]);
                    }
            }
        }

        float bias[2][2];
#pragma unroll
        for (int mt = 0; mt < 2; mt++)
#pragma unroll
            for (int h = 0; h < 2; h++) {
                const int og = oy * 64 + mo + mt * 16 + h * 8 + lg;
                bias[mt][h] = (og < 32) ? bq[og] : (og < 64 ? bk[og - 32] : bv[og - 64]);
            }
        const float scl = (oy == 0 && mo == 0) ? LOG2E : 1.0f;

        __syncthreads();
#pragma unroll
        for (int mt = 0; mt < 2; mt++)
#pragma unroll
            for (int nf = 0; nf < 8; nf++) {
                const int o0 = mo + mt * 16 + lg;
                const int n  = nb + nf * 8 + ll * 2;
                sts32(sbp + PJ_W + o0 * 560 + n * 2,
                      bf2((of[mt][nf][0] + bias[mt][0]) * scl,
                          (of[mt][nf][1] + bias[mt][0]) * scl));
                sts32(sbp + PJ_W + (o0 + 8) * 560 + n * 2,
                      bf2((of[mt][nf][2] + bias[mt][1]) * scl,
                          (of[mt][nf][3] + bias[mt][1]) * scl));
            }
        __syncthreads();

        if (oy == 0) {
            const int half = tid >> 7;
            const int t    = tid & 127;
            const int obase = half * 32;
            uint32_t val[32];
#pragma unroll
            for (int o = 0; o < 32; o++)
                val[o] = *(const uint32_t*)(psm + PJ_W + (obase + o) * 560 + t * 4);
            char* dst0 = (char*)((half ? g_k : g_q) + (((size_t)b << 12) + n0 + 2 * t) * 32);
#pragma unroll
            for (int rowp = 0; rowp < 2; rowp++) {
                const uint32_t sel = rowp ? 0x7632u : 0x5410u;
                uint32_t pk[16];
#pragma unroll
                for (int o2 = 0; o2 < 16; o2++)
                    pk[o2] = __byte_perm(val[2 * o2], val[2 * o2 + 1], sel);
                char* dst = dst0 + rowp * 64;
#pragma unroll
                for (int q4 = 0; q4 < 4; q4++)
                    *(uint4*)(dst + q4 * 16) =
                        make_uint4(pk[q4 * 4], pk[q4 * 4 + 1], pk[q4 * 4 + 2], pk[q4 * 4 + 3]);
            }
        } else {
#pragma unroll
            for (int r = 0; r < 8; r++) {
                const int idx = tid + r * 256;
                const int row = idx >> 5, q = idx & 31;
                const uint4 v = *(const uint4*)(psm + PJ_W + row * 560 + q * 16);
                char* dst = (char*)g_v +
                    (((size_t)(b * CDIM + (oy - 1) * 64 + row)) << 13) + n0 * 2 + q * 16;
                *(uint4*)dst = v;
            }
        }
    }
}

// ================= Kernel B: HMMA flash attention (anti-phased warp halves) =================
#define QS_OFF 0
#define KS_OFF 10240
#define K_STR  5120
#define PS_OFF 30720
#define P_STR  18432
#define RS_OFF 67584
#define VS_OFF 68608
#define V_STR  36864
#define SMEM_BYTES 216064

__global__ void __launch_bounds__(512, 1) attn_kernel(
    const float* __restrict__ x,
    const float* __restrict__ gamma,
    float* __restrict__ out)
{
    extern __shared__ char smc[];
    const uint32_t sb = smem_u32(smc);
    const int tid = threadIdx.x;
    const int w = tid >> 5, lane = tid & 31;
    const int lg = lane >> 2, ll = lane & 3;
    const int b = blockIdx.y, m0 = blockIdx.x * 128;

    const int s_mb = (w >> 1) * 16, s_nb = (w & 1) * 32;
    const int p_mb = (w >> 2) * 32, p_cb = (w & 3) * 64;

    const uint32_t a_off144 = (lane & 15) * 144 + ((lane >> 4) << 4);
    const uint32_t a_off80  = (lane & 15) * 80  + ((lane >> 4) << 4);
    const uint32_t b_off_v  = ((lane & 7) + ((lane >> 4) << 3)) * 144 + (((lane >> 3) & 1) << 4);
    const uint32_t b_off_k  = ((lane & 7) + ((lane >> 4) << 3)) * 80  + (((lane >> 3) & 1) << 4);

    const char* gq = (const char*)g_q + ((size_t)(b << 12) + m0) * 64;
    const char* gk = (const char*)g_k + ((size_t)b << 18);
    const char* gv = (const char*)g_v + (size_t)b * CDIM * 8192;

#define LOAD_KV(t2) do { \
    const int _sl = (t2) & 3; \
    if (tid < 256) \
        cp16(sb + KS_OFF + _sl * K_STR + (tid >> 2) * 80 + (tid & 3) * 16, \
             gk + (size_t)(t2) * 4096 + tid * 16); \
    _Pragma("unroll") \
    for (int _i = 0; _i < 4; _i++) { \
        const int _e = tid + _i * 512, _c = _e >> 3, _j = _e & 7; \
        cp16(sb + VS_OFF + _sl * V_STR + _c * 144 + _j * 16, \
             gv + (size_t)_c * 8192 + (size_t)(t2) * 128 + _j * 16); \
    } CP_COMMIT(); } while (0)

    cp16(sb + QS_OFF + (tid >> 2) * 80 + (tid & 3) * 16, gq + tid * 16);
    if (tid < 256)
        cp16(sb + KS_OFF + (tid >> 2) * 80 + (tid & 3) * 16, gk + tid * 16);
#pragma unroll
    for (int i = 0; i < 4; i++) {
        const int e = tid + i * 512, c = e >> 3, jj = e & 7;
        cp16(sb + VS_OFF + c * 144 + jj * 16, gv + (size_t)c * 8192 + jj * 16);
    }
    CP_COMMIT();
    LOAD_KV(1);
    CP_WAIT(0);
    __syncthreads();

    float of[2][8][4];
#pragma unroll
    for (int mt = 0; mt < 2; mt++)
#pragma unroll
        for (int nf = 0; nf < 8; nf++)
#pragma unroll
            for (int r = 0; r < 4; r++) of[mt][nf][r] = 0.0f;
    float rsA = 0.0f, rsB = 0.0f;

#define S_COMPUTE(TILE, sf) do { \
    const uint32_t kbt = sb + KS_OFF + ((TILE) & 3) * K_STR; \
    uint32_t bfr[2][2][4]; \
    _Pragma("unroll") \
    for (int ks = 0; ks < 2; ks++) \
        _Pragma("unroll") \
        for (int np = 0; np < 2; np++) \
            ldm_x4(kbt + (uint32_t)(s_nb + np * 16) * 80 + b_off_k + ks * 32, bfr[ks][np]); \
    _Pragma("unroll") \
    for (int ks = 0; ks < 2; ks++) { \
        uint32_t a[4]; \
        ldm_x4(sb + QS_OFF + (uint32_t)s_mb * 80 + a_off80 + ks * 32, a); \
        _Pragma("unroll") \
        for (int nf = 0; nf < 4; nf++) \
            mma16816(sf[nf], a, bfr[ks][nf >> 1][(nf & 1) * 2], \
                     bfr[ks][nf >> 1][(nf & 1) * 2 + 1]); \
    } } while (0)

#define SOFTMAX_Q(TILE, NF, sf) do { \
    const float p0 = ex2f(sf[NF][0]), p1 = ex2f(sf[NF][1]); \
    const float p2 = ex2f(sf[NF][2]), p3 = ex2f(sf[NF][3]); \
    const __nv_bfloat162 t01 = __floats2bfloat162_rn(p0, p1); \
    const __nv_bfloat162 t23 = __floats2bfloat162_rn(p2, p3); \
    const float2 f01 = __bfloat1622float2(t01); \
    const float2 f23 = __bfloat1622float2(t23); \
    rsA += f01.x + f01.y; \
    rsB += f23.x + f23.y; \
    const uint32_t pr0 = sb + PS_OFF + ((TILE) & 1) * P_STR + (s_mb + lg) * 144; \
    const int nb2 = (s_nb + (NF) * 8 + ll * 2) * 2; \
    sts32(pr0 + nb2, *(const uint32_t*)&t01); \
    sts32(pr0 + 8 * 144 + nb2, *(const uint32_t*)&t23); } while (0)

#define S_PHASE(TILE) do { \
    float sf[4][4]; \
    _Pragma("unroll") \
    for (int nf = 0; nf < 4; nf++) \
        _Pragma("unroll") \
        for (int r = 0; r < 4; r++) sf[nf][r] = 0.0f; \
    S_COMPUTE(TILE, sf); \
    _Pragma("unroll") \
    for (int nf = 0; nf < 4; nf++) SOFTMAX_Q(TILE, nf, sf); } while (0)

#define PV_PHASE(KT) do { \
    const uint32_t pt = sb + PS_OFF + ((KT) & 1) * P_STR; \
    const uint32_t vt = sb + VS_OFF + ((KT) & 3) * V_STR; \
    uint32_t pa[4][2][4]; \
    _Pragma("unroll") \
    for (int ks = 0; ks < 4; ks++) { \
        ldm_x4(pt + (uint32_t)p_mb * 144 + a_off144 + ks * 32, pa[ks][0]); \
        ldm_x4(pt + (uint32_t)(p_mb + 16) * 144 + a_off144 + ks * 32, pa[ks][1]); \
    } \
    _Pragma("unroll") \
    for (int np = 0; np < 4; np++) { \
        uint32_t vb[4][4]; \
        _Pragma("unroll") \
        for (int ks = 0; ks < 4; ks++) \
            ldm_x4(vt + (uint32_t)(p_cb + np * 16) * 144 + b_off_v + ks * 32, vb[ks]); \
        _Pragma("unroll") \
        for (int ks = 0; ks < 4; ks++) { \
            _Pragma("unroll") \
            for (int nf2 = 0; nf2 < 2; nf2++) { \
                const int nf = np * 2 + nf2; \
                mma16816(of[0][nf], pa[ks][0], vb[ks][nf2 * 2], vb[ks][nf2 * 2 + 1]); \
                mma16816(of[1][nf], pa[ks][1], vb[ks][nf2 * 2], vb[ks][nf2 * 2 + 1]); \
            } \
        } \
    } } while (0)

    S_PHASE(0);

    for (int kt = 0; kt < 64; kt++) {
        if (kt + 2 < 64) LOAD_KV(kt + 2);
        if (kt < 62) { CP_WAIT(1); } else { CP_WAIT(0); }
        __syncthreads();  // publishes P(kt); K/V(kt+1) ready; PV(kt-1) done by all

        const bool doS = (kt < 63);
        if ((w & 1) == 0) {
            if (doS) S_PHASE(kt + 1);
            PV_PHASE(kt);
        } else {
            PV_PHASE(kt);
            if (doS) S_PHASE(kt + 1);
        }
    }

    // ---- epilogue ----
    rsA += __shfl_xor_sync(0xffffffffu, rsA, 1);
    rsA += __shfl_xor_sync(0xffffffffu, rsA, 2);
    rsB += __shfl_xor_sync(0xffffffffu, rsB, 1);
    rsB += __shfl_xor_sync(0xffffffffu, rsB, 2);
    float* rowarr = (float*)(smc + RS_OFF);
    if (ll == 0) {
        rowarr[(s_mb + lg) * 2 + (w & 1)]     = rsA;
        rowarr[(s_mb + 8 + lg) * 2 + (w & 1)] = rsB;
    }
    __syncthreads();

    const float gm = gamma[0];
    float inv[4];
#pragma unroll
    for (int mt = 0; mt < 2; mt++)
#pragma unroll
        for (int h = 0; h < 2; h++) {
            const int r = p_mb + mt * 16 + h * 8 + lg;
            inv[mt * 2 + h] = gm / (rowarr[2 * r] + rowarr[2 * r + 1]);
        }

    float* ost = (float*)(smc + VS_OFF);
#pragma unroll 1
    for (int chunk = 0; chunk < 2; chunk++) {
        if (((w & 3) >> 1) == chunk) {
#pragma unroll
            for (int mt = 0; mt < 2; mt++)
#pragma unroll
                for (int nf = 0; nf < 8; nf++) {
                    const int cl = (p_cb - chunk * 128) + nf * 8 + ll * 2;
                    const int m = p_mb + mt * 16 + lg;
                    ost[cl * 132 + m]           = of[mt][nf][0] * inv[mt * 2];
                    ost[(cl + 1) * 132 + m]     = of[mt][nf][1] * inv[mt * 2];
                    ost[cl * 132 + m + 8]       = of[mt][nf][2] * inv[mt * 2 + 1];
                    ost[(cl + 1) * 132 + m + 8] = of[mt][nf][3] * inv[mt * 2 + 1];
                }
        }
        __syncthreads();
        const int m = tid & 127, cb = tid >> 7;
#pragma unroll 4
        for (int cc = 0; cc < 32; cc++) {
            const int cl = cc * 4 + cb;
            const int c = chunk * 128 + cl;
            const size_t off = ((size_t)b * CDIM + c) * NPOS + m0 + m;
            out[off] = ost[cl * 132 + m] + x[off];
        }
        __syncthreads();
    }
}

// ================= launch =================
extern "C" void kernel_launch(void* const* d_in, const int* in_sizes, int n_in,
                              void* d_out, int out_size)
{
    const float* x     = (const float*)d_in[0];
    const float* Wq    = (const float*)d_in[1];
    const float* bq    = (const float*)d_in[2];
    const float* Wk    = (const float*)d_in[3];
    const float* bk    = (const float*)d_in[4];
    const float* Wv    = (const float*)d_in[5];
    const float* bv    = (const float*)d_in[6];
    const float* gamma = (const float*)d_in[7];
    float* out = (float*)d_out;

    cudaFuncSetAttribute(proj_kernel, cudaFuncAttributeMaxDynamicSharedMemorySize,
                         PROJ_SMEM);
    proj_kernel<<<dim3(NPOS / 256, BATCH), 256, PROJ_SMEM>>>(x, Wq, bq, Wk, bk, Wv, bv);

    cudaFuncSetAttribute(attn_kernel, cudaFuncAttributeMaxDynamicSharedMemorySize,
                         SMEM_BYTES);
    attn_kernel<<<dim3(NPOS / 128, BATCH), 512, SMEM_BYTES>>>(x, gamma, out);
}

// round 16
// speedup vs baseline: 1.0706x; 1.0706x over previous
#include <cuda_runtime.h>
#include <cuda_bf16.h>
#include <cstdint>

#define BATCH 8
#define NPOS 4096
#define CDIM 256

// Scratch: Q bf16 [b][n][32] (pre-scaled by log2e), K bf16 [b][n][32],
// V channel-major bf16 [b][c][n].
__device__ __nv_bfloat16 g_q[(size_t)BATCH * NPOS * 32];
__device__ __nv_bfloat16 g_k[(size_t)BATCH * NPOS * 32];
__device__ __nv_bfloat16 g_v[(size_t)BATCH * CDIM * NPOS];

// ---------------- helpers ----------------
__device__ __forceinline__ uint32_t smem_u32(const void* p) {
    uint32_t a;
    asm("{ .reg .u64 t; cvta.to.shared.u64 t, %1; cvt.u32.u64 %0, t; }" : "=r"(a) : "l"(p));
    return a;
}
__device__ __forceinline__ float ex2f(float x) {
    float y; asm("ex2.approx.f32 %0, %1;" : "=f"(y) : "f"(x)); return y;
}
__device__ __forceinline__ void sts32(uint32_t a, uint32_t v) {
    asm volatile("st.shared.b32 [%0], %1;" :: "r"(a), "r"(v));
}
__device__ __forceinline__ void sts128(uint32_t a, uint32_t v0, uint32_t v1,
                                       uint32_t v2, uint32_t v3) {
    asm volatile("st.shared.v4.b32 [%0], {%1, %2, %3, %4};"
                 :: "r"(a), "r"(v0), "r"(v1), "r"(v2), "r"(v3));
}
__device__ __forceinline__ void cp16(uint32_t dst, const void* src) {
    asm volatile("cp.async.cg.shared.global [%0], [%1], 16;" :: "r"(dst), "l"(src));
}
#define CP_COMMIT() asm volatile("cp.async.commit_group;" ::: "memory")
#define CP_WAIT(N)  asm volatile("cp.async.wait_group %0;" :: "n"(N) : "memory")

__device__ __forceinline__ void ldm_x4(uint32_t addr, uint32_t* r) {
    asm volatile("ldmatrix.sync.aligned.m8n8.x4.shared.b16 {%0,%1,%2,%3}, [%4];"
                 : "=r"(r[0]), "=r"(r[1]), "=r"(r[2]), "=r"(r[3]) : "r"(addr));
}
__device__ __forceinline__ void mma16816(float* c, const uint32_t* a, uint32_t b0, uint32_t b1) {
    asm volatile(
        "mma.sync.aligned.m16n8k16.row.col.f32.bf16.bf16.f32 "
        "{%0,%1,%2,%3}, {%4,%5,%6,%7}, {%8,%9}, {%0,%1,%2,%3};"
        : "+f"(c[0]), "+f"(c[1]), "+f"(c[2]), "+f"(c[3])
        : "r"(a[0]), "r"(a[1]), "r"(a[2]), "r"(a[3]), "r"(b0), "r"(b1));
}
__device__ __forceinline__ uint32_t bf2(float a, float b) {
    const __nv_bfloat162 t = __floats2bfloat162_rn(a, b);
    return *(const uint32_t*)&t;
}

#define LOG2E 1.4426950408889634f

// ================= Kernel A: fused transpose + projections on HMMA (R13) =================
#define PJ_XS  0
#define PJ_W   131072
#define PROJ_SMEM 166912

__global__ void __launch_bounds__(256) proj_kernel(
    const float* __restrict__ x,
    const float* __restrict__ Wq, const float* __restrict__ bq,
    const float* __restrict__ Wk, const float* __restrict__ bk,
    const float* __restrict__ Wv, const float* __restrict__ bv)
{
    extern __shared__ char psm[];
    const uint32_t sbp = smem_u32(psm);
    const int tid = threadIdx.x;
    const int w = tid >> 5, lane = tid & 31;
    const int lg = lane >> 2, ll = lane & 3;
    const int b  = blockIdx.y;
    const int n0 = blockIdx.x * 256;

    const int mo = (w & 1) * 32;
    const int nb = (w >> 1) * 64;

    const uint32_t a_off_w = (lane & 15) * 528 + ((lane >> 4) << 4);
    const int xrow = (lane & 7) + ((lane >> 4) << 3);
    const int xhb  = (lane >> 3) & 1;

    // ---- Phase X: transpose x -> xs ----
    {
        const float* xg = x + (((size_t)b * CDIM) << 12) + n0 + tid;
        const uint32_t rowbase = sbp + PJ_XS + tid * 512;
        const int nx7 = tid & 7;
#pragma unroll 1
        for (int ci = 0; ci < 8; ci++) {
            float xv[32];
#pragma unroll
            for (int c = 0; c < 32; c++)
                xv[c] = xg[((size_t)(ci * 32 + c)) << 12];
            uint32_t pk[16];
#pragma unroll
            for (int e = 0; e < 16; e++) pk[e] = bf2(xv[2 * e], xv[2 * e + 1]);
#pragma unroll
            for (int q = 0; q < 4; q++)
                sts128(rowbase + (uint32_t)(((ci * 4 + q) ^ nx7) << 4),
                       pk[4 * q], pk[4 * q + 1], pk[4 * q + 2], pk[4 * q + 3]);
        }
    }

#pragma unroll 1
    for (int oy = 0; oy < 5; oy++) {
        __syncthreads();

        {
            const int ob = oy * 64;
#pragma unroll
            for (int r = 0; r < 8; r++) {
                const int idx = tid + r * 256;
                const int row = idx >> 5;
                const int cq  = (idx & 31) * 8;
                const int og  = ob + row;
                const float* wrow;
                if (og < 32)      wrow = Wq + og * CDIM;
                else if (og < 64) wrow = Wk + (og - 32) * CDIM;
                else              wrow = Wv + (og - 64) * CDIM;
                const float4 v0 = *(const float4*)(wrow + cq);
                const float4 v1 = *(const float4*)(wrow + cq + 4);
                const uint32_t base = sbp + PJ_W + row * 528 + cq * 2;
                sts32(base + 0,  bf2(v0.x, v0.y));
                sts32(base + 4,  bf2(v0.z, v0.w));
                sts32(base + 8,  bf2(v1.x, v1.y));
                sts32(base + 12, bf2(v1.z, v1.w));
            }
        }
        __syncthreads();

        float of[2][8][4];
#pragma unroll
        for (int mt = 0; mt < 2; mt++)
#pragma unroll
            for (int nf = 0; nf < 8; nf++)
#pragma unroll
                for (int r = 0; r < 4; r++) of[mt][nf][r] = 0.0f;

#pragma unroll 1
        for (int i = 0; i < 8; i++) {
            uint32_t afr[2][2][4];
#pragma unroll
            for (int mt = 0; mt < 2; mt++)
#pragma unroll
                for (int kk = 0; kk < 2; kk++)
                    ldm_x4(sbp + PJ_W + (uint32_t)(mo + mt * 16) * 528 + a_off_w +
                               i * 64 + kk * 32,
                           afr[mt][kk]);
#pragma unroll
            for (int np = 0; np < 4; np++) {
                const int row = nb + np * 16 + xrow;
                const uint32_t rb = sbp + PJ_XS + (uint32_t)row * 512;
                const int r7 = row & 7;
                uint32_t bfr[2][4];
                ldm_x4(rb + (uint32_t)(((i * 4 + 0 + xhb) ^ r7) << 4), bfr[0]);
                ldm_x4(rb + (uint32_t)(((i * 4 + 2 + xhb) ^ r7) << 4), bfr[1]);
#pragma unroll
                for (int mt = 0; mt < 2; mt++)
#pragma unroll
                    for (int nf2 = 0; nf2 < 2; nf2++) {
                        const int nf = np * 2 + nf2;
                        mma16816(of[mt][nf], afr[mt][0], bfr[0][nf2 * 2], bfr[0][nf2 * 2 + 1]);
                        mma16816(of[mt][nf], afr[mt][1], bfr[1][nf2 * 2], bfr[1][nf2 * 2 + 1]);
                    }
            }
        }

        float bias[2][2];
#pragma unroll
        for (int mt = 0; mt < 2; mt++)
#pragma unroll
            for (int h = 0; h < 2; h++) {
                const int og = oy * 64 + mo + mt * 16 + h * 8 + lg;
                bias[mt][h] = (og < 32) ? bq[og] : (og < 64 ? bk[og - 32] : bv[og - 64]);
            }
        const float scl = (oy == 0 && mo == 0) ? LOG2E : 1.0f;

        __syncthreads();
#pragma unroll
        for (int mt = 0; mt < 2; mt++)
#pragma unroll
            for (int nf = 0; nf < 8; nf++) {
                const int o0 = mo + mt * 16 + lg;
                const int n  = nb + nf * 8 + ll * 2;
                sts32(sbp + PJ_W + o0 * 560 + n * 2,
                      bf2((of[mt][nf][0] + bias[mt][0]) * scl,
                          (of[mt][nf][1] + bias[mt][0]) * scl));
                sts32(sbp + PJ_W + (o0 + 8) * 560 + n * 2,
                      bf2((of[mt][nf][2] + bias[mt][1]) * scl,
                          (of[mt][nf][3] + bias[mt][1]) * scl));
            }
        __syncthreads();

        if (oy == 0) {
            const int half = tid >> 7;
            const int t    = tid & 127;
            const int obase = half * 32;
            uint32_t val[32];
#pragma unroll
            for (int o = 0; o < 32; o++)
                val[o] = *(const uint32_t*)(psm + PJ_W + (obase + o) * 560 + t * 4);
            char* dst0 = (char*)((half ? g_k : g_q) + (((size_t)b << 12) + n0 + 2 * t) * 32);
#pragma unroll
            for (int rowp = 0; rowp < 2; rowp++) {
                const uint32_t sel = rowp ? 0x7632u : 0x5410u;
                uint32_t pk[16];
#pragma unroll
                for (int o2 = 0; o2 < 16; o2++)
                    pk[o2] = __byte_perm(val[2 * o2], val[2 * o2 + 1], sel);
                char* dst = dst0 + rowp * 64;
#pragma unroll
                for (int q4 = 0; q4 < 4; q4++)
                    *(uint4*)(dst + q4 * 16) =
                        make_uint4(pk[q4 * 4], pk[q4 * 4 + 1], pk[q4 * 4 + 2], pk[q4 * 4 + 3]);
            }
        } else {
#pragma unroll
            for (int r = 0; r < 8; r++) {
                const int idx = tid + r * 256;
                const int row = idx >> 5, q = idx & 31;
                const uint4 v = *(const uint4*)(psm + PJ_W + row * 560 + q * 16);
                char* dst = (char*)g_v +
                    (((size_t)(b * CDIM + (oy - 1) * 64 + row)) << 13) + n0 * 2 + q * 16;
                *(uint4*)dst = v;
            }
        }
    }
}

// ================= Kernel B: HMMA flash attention (R14 + unroll 4) =================
#define QS_OFF 0
#define KS_OFF 10240
#define K_STR  5120
#define PS_OFF 30720
#define P_STR  18432
#define RS_OFF 67584
#define VS_OFF 68608
#define V_STR  36864
#define SMEM_BYTES 216064

__global__ void __launch_bounds__(512, 1) attn_kernel(
    const float* __restrict__ x,
    const float* __restrict__ gamma,
    float* __restrict__ out)
{
    extern __shared__ char smc[];
    const uint32_t sb = smem_u32(smc);
    const int tid = threadIdx.x;
    const int w = tid >> 5, lane = tid & 31;
    const int lg = lane >> 2, ll = lane & 3;
    const int b = blockIdx.y, m0 = blockIdx.x * 128;

    const int s_mb = (w >> 1) * 16, s_nb = (w & 1) * 32;
    const int p_mb = (w >> 2) * 32, p_cb = (w & 3) * 64;

    const uint32_t a_off144 = (lane & 15) * 144 + ((lane >> 4) << 4);
    const uint32_t a_off80  = (lane & 15) * 80  + ((lane >> 4) << 4);
    const uint32_t b_off_v  = ((lane & 7) + ((lane >> 4) << 3)) * 144 + (((lane >> 3) & 1) << 4);
    const uint32_t b_off_k  = ((lane & 7) + ((lane >> 4) << 3)) * 80  + (((lane >> 3) & 1) << 4);

    const char* gq = (const char*)g_q + ((size_t)(b << 12) + m0) * 64;
    const char* gk = (const char*)g_k + ((size_t)b << 18);
    const char* gv = (const char*)g_v + (size_t)b * CDIM * 8192;

#define LOAD_KV(t2) do { \
    const int _sl = (t2) & 3; \
    if (tid < 256) \
        cp16(sb + KS_OFF + _sl * K_STR + (tid >> 2) * 80 + (tid & 3) * 16, \
             gk + (size_t)(t2) * 4096 + tid * 16); \
    _Pragma("unroll") \
    for (int _i = 0; _i < 4; _i++) { \
        const int _e = tid + _i * 512, _c = _e >> 3, _j = _e & 7; \
        cp16(sb + VS_OFF + _sl * V_STR + _c * 144 + _j * 16, \
             gv + (size_t)_c * 8192 + (size_t)(t2) * 128 + _j * 16); \
    } CP_COMMIT(); } while (0)

    cp16(sb + QS_OFF + (tid >> 2) * 80 + (tid & 3) * 16, gq + tid * 16);
    if (tid < 256)
        cp16(sb + KS_OFF + (tid >> 2) * 80 + (tid & 3) * 16, gk + tid * 16);
#pragma unroll
    for (int i = 0; i < 4; i++) {
        const int e = tid + i * 512, c = e >> 3, jj = e & 7;
        cp16(sb + VS_OFF + c * 144 + jj * 16, gv + (size_t)c * 8192 + jj * 16);
    }
    CP_COMMIT();
    LOAD_KV(1);
    CP_WAIT(0);
    __syncthreads();

    float of[2][8][4];
#pragma unroll
    for (int mt = 0; mt < 2; mt++)
#pragma unroll
        for (int nf = 0; nf < 8; nf++)
#pragma unroll
            for (int r = 0; r < 4; r++) of[mt][nf][r] = 0.0f;
    float rsA = 0.0f, rsB = 0.0f;

#define S_COMPUTE(TILE, sf) do { \
    const uint32_t kbt = sb + KS_OFF + ((TILE) & 3) * K_STR; \
    uint32_t bfr[2][2][4]; \
    _Pragma("unroll") \
    for (int ks = 0; ks < 2; ks++) \
        _Pragma("unroll") \
        for (int np = 0; np < 2; np++) \
            ldm_x4(kbt + (uint32_t)(s_nb + np * 16) * 80 + b_off_k + ks * 32, bfr[ks][np]); \
    _Pragma("unroll") \
    for (int ks = 0; ks < 2; ks++) { \
        uint32_t a[4]; \
        ldm_x4(sb + QS_OFF + (uint32_t)s_mb * 80 + a_off80 + ks * 32, a); \
        _Pragma("unroll") \
        for (int nf = 0; nf < 4; nf++) \
            mma16816(sf[nf], a, bfr[ks][nf >> 1][(nf & 1) * 2], \
                     bfr[ks][nf >> 1][(nf & 1) * 2 + 1]); \
    } } while (0)

#define SOFTMAX_Q(TILE, NF, sf) do { \
    const float p0 = ex2f(sf[NF][0]), p1 = ex2f(sf[NF][1]); \
    const float p2 = ex2f(sf[NF][2]), p3 = ex2f(sf[NF][3]); \
    const __nv_bfloat162 t01 = __floats2bfloat162_rn(p0, p1); \
    const __nv_bfloat162 t23 = __floats2bfloat162_rn(p2, p3); \
    const float2 f01 = __bfloat1622float2(t01); \
    const float2 f23 = __bfloat1622float2(t23); \
    rsA += f01.x + f01.y; \
    rsB += f23.x + f23.y; \
    const uint32_t pr0 = sb + PS_OFF + ((TILE) & 1) * P_STR + (s_mb + lg) * 144; \
    const int nb2 = (s_nb + (NF) * 8 + ll * 2) * 2; \
    sts32(pr0 + nb2, *(const uint32_t*)&t01); \
    sts32(pr0 + 8 * 144 + nb2, *(const uint32_t*)&t23); } while (0)

    {
        float sf[4][4];
#pragma unroll
        for (int nf = 0; nf < 4; nf++)
#pragma unroll
            for (int r = 0; r < 4; r++) sf[nf][r] = 0.0f;
        S_COMPUTE(0, sf);
#pragma unroll
        for (int nf = 0; nf < 4; nf++) SOFTMAX_Q(0, nf, sf);
    }

#pragma unroll 4
    for (int kt = 0; kt < 64; kt++) {
        if (kt + 2 < 64) LOAD_KV(kt + 2);
        if (kt < 62) { CP_WAIT(1); } else { CP_WAIT(0); }
        __syncthreads();  // publishes P(kt); K/V(kt+1) ready; PV(kt-1) done by all

        // ---- S(kt+1) + softmax (sf dies before PV) ----
        if (kt < 63) {
            float sf[4][4];
#pragma unroll
            for (int nf = 0; nf < 4; nf++)
#pragma unroll
                for (int r = 0; r < 4; r++) sf[nf][r] = 0.0f;
            S_COMPUTE(kt + 1, sf);
#pragma unroll
            for (int nf = 0; nf < 4; nf++) SOFTMAX_Q(kt + 1, nf, sf);
        }

        // ---- PV(kt): hoisted P fragments, per-np V loads independent of MMAs ----
        const uint32_t pt = sb + PS_OFF + (kt & 1) * P_STR;
        const uint32_t vt = sb + VS_OFF + (kt & 3) * V_STR;
        uint32_t pa[4][2][4];
#pragma unroll
        for (int ks = 0; ks < 4; ks++) {
            ldm_x4(pt + (uint32_t)p_mb * 144 + a_off144 + ks * 32, pa[ks][0]);
            ldm_x4(pt + (uint32_t)(p_mb + 16) * 144 + a_off144 + ks * 32, pa[ks][1]);
        }
#pragma unroll
        for (int np = 0; np < 4; np++) {
            uint32_t vb[4][4];
#pragma unroll
            for (int ks = 0; ks < 4; ks++)
                ldm_x4(vt + (uint32_t)(p_cb + np * 16) * 144 + b_off_v + ks * 32, vb[ks]);
#pragma unroll
            for (int ks = 0; ks < 4; ks++) {
#pragma unroll
                for (int nf2 = 0; nf2 < 2; nf2++) {
                    const int nf = np * 2 + nf2;
                    mma16816(of[0][nf], pa[ks][0], vb[ks][nf2 * 2], vb[ks][nf2 * 2 + 1]);
                    mma16816(of[1][nf], pa[ks][1], vb[ks][nf2 * 2], vb[ks][nf2 * 2 + 1]);
                }
            }
        }
    }

    // ---- epilogue ----
    rsA += __shfl_xor_sync(0xffffffffu, rsA, 1);
    rsA += __shfl_xor_sync(0xffffffffu, rsA, 2);
    rsB += __shfl_xor_sync(0xffffffffu, rsB, 1);
    rsB += __shfl_xor_sync(0xffffffffu, rsB, 2);
    float* rowarr = (float*)(smc + RS_OFF);
    if (ll == 0) {
        rowarr[(s_mb + lg) * 2 + (w & 1)]     = rsA;
        rowarr[(s_mb + 8 + lg) * 2 + (w & 1)] = rsB;
    }
    __syncthreads();

    const float gm = gamma[0];
    float inv[4];
#pragma unroll
    for (int mt = 0; mt < 2; mt++)
#pragma unroll
        for (int h = 0; h < 2; h++) {
            const int r = p_mb + mt * 16 + h * 8 + lg;
            inv[mt * 2 + h] = gm / (rowarr[2 * r] + rowarr[2 * r + 1]);
        }

    float* ost = (float*)(smc + VS_OFF);
#pragma unroll 1
    for (int chunk = 0; chunk < 2; chunk++) {
        if (((w & 3) >> 1) == chunk) {
#pragma unroll
            for (int mt = 0; mt < 2; mt++)
#pragma unroll
                for (int nf = 0; nf < 8; nf++) {
                    const int cl = (p_cb - chunk * 128) + nf * 8 + ll * 2;
                    const int m = p_mb + mt * 16 + lg;
                    ost[cl * 132 + m]           = of[mt][nf][0] * inv[mt * 2];
                    ost[(cl + 1) * 132 + m]     = of[mt][nf][1] * inv[mt * 2];
                    ost[cl * 132 + m + 8]       = of[mt][nf][2] * inv[mt * 2 + 1];
                    ost[(cl + 1) * 132 + m + 8] = of[mt][nf][3] * inv[mt * 2 + 1];
                }
        }
        __syncthreads();
        const int m = tid & 127, cb = tid >> 7;
#pragma unroll 4
        for (int cc = 0; cc < 32; cc++) {
            const int cl = cc * 4 + cb;
            const int c = chunk * 128 + cl;
            const size_t off = ((size_t)b * CDIM + c) * NPOS + m0 + m;
            out[off] = ost[cl * 132 + m] + x[off];
        }
        __syncthreads();
    }
}

// ================= launch =================
extern "C" void kernel_launch(void* const* d_in, const int* in_sizes, int n_in,
                              void* d_out, int out_size)
{
    const float* x     = (const float*)d_in[0];
    const float* Wq    = (const float*)d_in[1];
    const float* bq    = (const float*)d_in[2];
    const float* Wk    = (const float*)d_in[3];
    const float* bk    = (const float*)d_in[4];
    const float* Wv    = (const float*)d_in[5];
    const float* bv    = (const float*)d_in[6];
    const float* gamma = (const float*)d_in[7];
    float* out = (float*)d_out;

    cudaFuncSetAttribute(proj_kernel, cudaFuncAttributeMaxDynamicSharedMemorySize,
                         PROJ_SMEM);
    proj_kernel<<<dim3(NPOS / 256, BATCH), 256, PROJ_SMEM>>>(x, Wq, bq, Wk, bk, Wv, bv);

    cudaFuncSetAttribute(attn_kernel, cudaFuncAttributeMaxDynamicSharedMemorySize,
                         SMEM_BYTES);
    attn_kernel<<<dim3(NPOS / 128, BATCH), 512, SMEM_BYTES>>>(x, gamma, out);
}